// round 7
// baseline (speedup 1.0000x reference)
#include <cuda_runtime.h>
#include <cstdint>

#define BB 64
#define NN 512
#define HH 128
#define NCOG 72
#define NRB 72

// Scratch (allocation-free __device__ globals).
// g_wc: COMPACTED w rows: g_wc[b][ip][jc] = relu(domain[cog,r]-d) at
//       (i=list[ip], j=list[jc]); rows zero-padded to cnt32.
// __align__(16): base must be 16B-aligned for the float4 (LDG/STG.128) paths —
// the default guarantee for a __device__ float array is only 4B.
__device__ __align__(16) float g_wc[(size_t)BB * NN * NN];  // 64 MB reserved, ~17 MB touched
__device__ int      g_jlist[BB][NN];             // active indices per batch (sorted)
__device__ int      g_jcnt[BB];
__device__ unsigned g_maxbits;                   // global max as uint bits (vals >= 0)

// ---------------------------------------------------------------------------
// Zero the output (inactive rows are never written by the GEMM).
// ---------------------------------------------------------------------------
__global__ void k_zero_out(float4* __restrict__ out, int n4) {
    int idx = blockIdx.x * blockDim.x + threadIdx.x;
    int stride = gridDim.x * blockDim.x;
    float4 z = make_float4(0.f, 0.f, 0.f, 0.f);
    for (int i = idx; i < n4; i += stride) out[i] = z;
}

// ---------------------------------------------------------------------------
// Per batch: build sorted list of active indices (mask!=0). Reset global max.
// Same list serves rows (i) and cols (j): mask is shared.
// ---------------------------------------------------------------------------
__global__ void k_compact(const float* __restrict__ mask) {
    int b = blockIdx.x;
    int j = threadIdx.x;          // 0..511
    if (b == 0 && j == 0) g_maxbits = 0u;

    bool act = (mask[b * NN + j] != 0.0f);
    unsigned ball = __ballot_sync(0xffffffffu, act);

    __shared__ int wcnt[16], wbase[16];
    int warp = j >> 5, lane = j & 31;
    if (lane == 0) wcnt[warp] = __popc(ball);
    __syncthreads();
    if (j == 0) {
        int s = 0;
        for (int w = 0; w < 16; w++) { wbase[w] = s; s += wcnt[w]; }
        g_jcnt[b] = s;
    }
    __syncthreads();
    if (act) {
        int pos = wbase[warp] + __popc(ball & ((1u << lane) - 1u));
        g_jlist[b][pos] = j;
    }
}

// ---------------------------------------------------------------------------
// Build compacted w rows + fold global max.
// Block (ip, b): one active row i = list[ip]. 128 threads x 4 jc positions.
// Gathered (ascending-index) reads of rmat/cog/dmat; dense float4 row writes.
// ---------------------------------------------------------------------------
__global__ void __launch_bounds__(128) k_build_w(
    const int*   __restrict__ rmat,
    const float* __restrict__ dmat,
    const int*   __restrict__ cog,
    const float* __restrict__ domain)
{
    int ip = blockIdx.x, b = blockIdx.y;
    int cnt = g_jcnt[b];
    if (ip >= cnt) return;

    __shared__ int s_jl[NN];
    int t = threadIdx.x;
    #pragma unroll
    for (int q = 0; q < 4; q++) {
        int jc = t + q * 128;
        s_jl[jc] = (jc < cnt) ? g_jlist[b][jc] : 0;
    }
    __syncthreads();

    int i = g_jlist[b][ip];
    size_t src = ((size_t)(b * NN + i)) * NN;      // raw row base
    size_t dst = ((size_t)(b * NN + ip)) * NN;     // compact row base
    int cnt32 = (cnt + 31) & ~31;

    int jc0 = t * 4;
    float w[4];
    float lm = 0.f;
    #pragma unroll
    for (int q = 0; q < 4; q++) {
        int jc = jc0 + q;
        float v = 0.f;
        if (jc < cnt) {
            int j = s_jl[jc];
            float dom = __ldg(domain + __ldg(cog + src + j) * NRB + __ldg(rmat + src + j));
            v = fmaxf(dom - __ldg(dmat + src + j), 0.f);
        }
        w[q] = v;
        lm = fmaxf(lm, v);
    }
    if (jc0 < cnt32)
        *(float4*)(g_wc + dst + jc0) = make_float4(w[0], w[1], w[2], w[3]);

    #pragma unroll
    for (int off = 16; off; off >>= 1)
        lm = fmaxf(lm, __shfl_xor_sync(0xffffffffu, lm, off));
    __shared__ float smax[4];
    if ((t & 31) == 0) smax[t >> 5] = lm;
    __syncthreads();
    if (t == 0) {
        float bm = fmaxf(fmaxf(smax[0], smax[1]), fmaxf(smax[2], smax[3]));
        atomicMax(&g_maxbits, __float_as_uint(bm));
    }
}

// ---------------------------------------------------------------------------
// Compacted GEMM: out[b, list[ip], h] = inv_max * sum_jc wc[b,ip,jc] * h_t[list[jc], b, h]
// Block = 64 compacted i-rows x 128 h for one batch. 256 threads.
// Per thread: 4 i (ty=tid>>4) x 8 h (tx=tid&15). k-tile 32.
// sW padded to stride 36: 16B-aligned rows (float4 STS legal) AND
// conflict-free broadcasts (bank delta 16 between the 2 rows/warp).
// ---------------------------------------------------------------------------
__global__ void __launch_bounds__(256, 3) k_gemm(
    const float* __restrict__ h_t,
    float*       __restrict__ out)
{
    int b   = blockIdx.y;
    int cnt = g_jcnt[b];
    int ip0 = blockIdx.x * 64;
    if (ip0 >= cnt) return;
    int cnt32 = (cnt + 31) & ~31;

    int tid = threadIdx.x;
    int tx  = tid & 15;                 // h octet (8 floats)
    int ty  = tid >> 4;                 // i quad (4 rows)

    __shared__ float sW[64][36];        // stride 36: aligned + conflict-free
    __shared__ float sH[32][128];
    __shared__ int   s_jl[NN];
    __shared__ int   s_il[64];

    // preload full jlist once (H-gather indices for every tile)
    #pragma unroll
    for (int q = 0; q < 2; q++) {
        int jc = tid + q * 256;
        s_jl[jc] = (jc < cnt) ? g_jlist[b][jc] : 0;
    }
    if (tid < 64) {
        int ip = ip0 + tid;
        s_il[tid] = (ip < cnt) ? g_jlist[b][ip] : 0;
    }

    float acc[4][8];
    #pragma unroll
    for (int a = 0; a < 4; a++)
        #pragma unroll
        for (int c = 0; c < 8; c++) acc[a][c] = 0.f;

    const float* hb = h_t + (size_t)b * HH;             // h_t[j,b,h]
    const float* wb = g_wc + ((size_t)b * NN + ip0) * NN;

    for (int kc0 = 0; kc0 < cnt32; kc0 += 32) {
        __syncthreads();   // previous tile fully consumed

        // W tile: 64 x 32 dense. 512 quads, 2 per thread.
        #pragma unroll
        for (int rep = 0; rep < 2; rep++) {
            int q  = rep * 256 + tid;
            int ii = q >> 3;
            int kq = q & 7;
            float4 v = make_float4(0.f, 0.f, 0.f, 0.f);
            if (ip0 + ii < cnt)
                v = *(const float4*)(wb + (size_t)ii * NN + kc0 + kq * 4);
            *(float4*)(&sW[ii][kq * 4]) = v;
        }
        // H tile: 32 gathered rows x 128 floats. 1024 quads, 4 per thread.
        #pragma unroll
        for (int rep = 0; rep < 4; rep++) {
            int e  = rep * 256 + tid;
            int kk = e >> 5;
            int h4 = e & 31;
            int j  = s_jl[kc0 + kk];
            float4 hv = *(const float4*)(hb + (size_t)j * (BB * HH) + h4 * 4);
            *(float4*)(&sH[kk][h4 * 4]) = hv;
        }
        __syncthreads();

        #pragma unroll
        for (int kk = 0; kk < 32; kk++) {
            float4 h0 = *(const float4*)(&sH[kk][tx * 8]);
            float4 h1 = *(const float4*)(&sH[kk][tx * 8 + 4]);
            #pragma unroll
            for (int a = 0; a < 4; a++) {
                float wv = sW[ty * 4 + a][kk];
                acc[a][0] = fmaf(wv, h0.x, acc[a][0]);
                acc[a][1] = fmaf(wv, h0.y, acc[a][1]);
                acc[a][2] = fmaf(wv, h0.z, acc[a][2]);
                acc[a][3] = fmaf(wv, h0.w, acc[a][3]);
                acc[a][4] = fmaf(wv, h1.x, acc[a][4]);
                acc[a][5] = fmaf(wv, h1.y, acc[a][5]);
                acc[a][6] = fmaf(wv, h1.z, acc[a][6]);
                acc[a][7] = fmaf(wv, h1.w, acc[a][7]);
            }
        }
    }

    float inv = 1.0f / __uint_as_float(g_maxbits);
    #pragma unroll
    for (int a = 0; a < 4; a++) {
        int ipl = ty * 4 + a;
        if (ip0 + ipl < cnt) {
            int i = s_il[ipl];
            float* op = out + ((size_t)(b * NN + i)) * HH + tx * 8;
            float4 o0 = make_float4(acc[a][0] * inv, acc[a][1] * inv,
                                    acc[a][2] * inv, acc[a][3] * inv);
            float4 o1 = make_float4(acc[a][4] * inv, acc[a][5] * inv,
                                    acc[a][6] * inv, acc[a][7] * inv);
            *(float4*)(op)     = o0;
            *(float4*)(op + 4) = o1;
        }
    }
}

// ---------------------------------------------------------------------------
extern "C" void kernel_launch(void* const* d_in, const int* in_sizes, int n_in,
                              void* d_out, int out_size)
{
    const float* h_t    = (const float*)d_in[0];   // [N,B,H]
    const int*   r_mat  = (const int*)  d_in[1];   // [B,N,N]
    const float* d_mat  = (const float*)d_in[2];   // [B,N,N]
    const float* mask   = (const float*)d_in[3];   // [B,N]
    const int*   cog    = (const int*)  d_in[4];   // [B,N,N]
    const float* domain = (const float*)d_in[5];   // [72,72]
    float* out = (float*)d_out;                    // [B,N,H]

    k_zero_out<<<1024, 256>>>((float4*)out, out_size / 4);
    k_compact<<<BB, NN>>>(mask);
    dim3 g1(NN, BB);
    k_build_w<<<g1, 128>>>(r_mat, d_mat, cog, domain);
    dim3 g2(NN / 64, BB);
    k_gemm<<<g2, 256>>>(h_t, out);
}

// round 8
// speedup vs baseline: 1.2533x; 1.2533x over previous
#include <cuda_runtime.h>
#include <cstdint>

#define BB 64
#define NN 512
#define HH 128
#define NCOG 72
#define NRB 72

// Scratch (allocation-free __device__ globals).
__device__ __align__(16) float g_wc[(size_t)BB * NN * NN];  // compacted w rows
__device__ int      g_jlist[BB][NN];
__device__ int      g_jcnt[BB];
__device__ unsigned g_maxbits;

// ---------------------------------------------------------------------------
__global__ void k_zero_out(float4* __restrict__ out, int n4) {
    int idx = blockIdx.x * blockDim.x + threadIdx.x;
    int stride = gridDim.x * blockDim.x;
    float4 z = make_float4(0.f, 0.f, 0.f, 0.f);
    for (int i = idx; i < n4; i += stride) out[i] = z;
}

// ---------------------------------------------------------------------------
__global__ void k_compact(const float* __restrict__ mask) {
    int b = blockIdx.x;
    int j = threadIdx.x;
    if (b == 0 && j == 0) g_maxbits = 0u;

    bool act = (mask[b * NN + j] != 0.0f);
    unsigned ball = __ballot_sync(0xffffffffu, act);

    __shared__ int wcnt[16], wbase[16];
    int warp = j >> 5, lane = j & 31;
    if (lane == 0) wcnt[warp] = __popc(ball);
    __syncthreads();
    if (j == 0) {
        int s = 0;
        for (int w = 0; w < 16; w++) { wbase[w] = s; s += wcnt[w]; }
        g_jcnt[b] = s;
    }
    __syncthreads();
    if (act) {
        int pos = wbase[warp] + __popc(ball & ((1u << lane) - 1u));
        g_jlist[b][pos] = j;
    }
}

// ---------------------------------------------------------------------------
// Build compacted w rows. DENSE coalesced reads of rmat/cog/dmat (int4/float4),
// compaction via smem staging (s_pos scatter), compact float4 writes.
// Block (ip, b): one active row i = list[ip]; 128 threads x 4 j each.
// ---------------------------------------------------------------------------
__global__ void __launch_bounds__(128) k_build_w(
    const int*   __restrict__ rmat,
    const float* __restrict__ dmat,
    const int*   __restrict__ cog,
    const float* __restrict__ domain)
{
    int ip = blockIdx.x, b = blockIdx.y;
    int cnt = g_jcnt[b];
    if (ip >= cnt) return;

    __shared__ int s_pos[NN];
    __shared__ __align__(16) float s_stage[NN];
    int t = threadIdx.x;
    #pragma unroll
    for (int q = 0; q < 4; q++) {
        s_pos[t + q * 128]   = -1;
        s_stage[t + q * 128] = 0.f;
    }
    __syncthreads();
    #pragma unroll
    for (int q = 0; q < 4; q++) {
        int jc = t + q * 128;
        if (jc < cnt) s_pos[g_jlist[b][jc]] = jc;
    }
    __syncthreads();

    int i = g_jlist[b][ip];
    size_t src = ((size_t)(b * NN + i)) * NN;
    int j0 = t * 4;

    int4   rv = *(const int4*)(rmat + src + j0);
    int4   cv = *(const int4*)(cog  + src + j0);
    float4 dv = *(const float4*)(dmat + src + j0);

    float w0 = fmaxf(__ldg(domain + cv.x * NRB + rv.x) - dv.x, 0.f);
    float w1 = fmaxf(__ldg(domain + cv.y * NRB + rv.y) - dv.y, 0.f);
    float w2 = fmaxf(__ldg(domain + cv.z * NRB + rv.z) - dv.z, 0.f);
    float w3 = fmaxf(__ldg(domain + cv.w * NRB + rv.w) - dv.w, 0.f);

    float lm = 0.f;
    int p0 = s_pos[j0 + 0], p1 = s_pos[j0 + 1], p2 = s_pos[j0 + 2], p3 = s_pos[j0 + 3];
    if (p0 >= 0) { s_stage[p0] = w0; lm = fmaxf(lm, w0); }
    if (p1 >= 0) { s_stage[p1] = w1; lm = fmaxf(lm, w1); }
    if (p2 >= 0) { s_stage[p2] = w2; lm = fmaxf(lm, w2); }
    if (p3 >= 0) { s_stage[p3] = w3; lm = fmaxf(lm, w3); }

    #pragma unroll
    for (int off = 16; off; off >>= 1)
        lm = fmaxf(lm, __shfl_xor_sync(0xffffffffu, lm, off));
    __shared__ float smax[4];
    if ((t & 31) == 0) smax[t >> 5] = lm;
    __syncthreads();                 // also publishes s_stage
    if (t == 0) {
        float bm = fmaxf(fmaxf(smax[0], smax[1]), fmaxf(smax[2], smax[3]));
        atomicMax(&g_maxbits, __float_as_uint(bm));
    }

    size_t dst = ((size_t)(b * NN + ip)) * NN;
    int cnt32 = (cnt + 31) & ~31;
    if (j0 < cnt32)
        *(float4*)(g_wc + dst + j0) = *(const float4*)(s_stage + j0);
}

// ---------------------------------------------------------------------------
// Compacted GEMM. Tile 32i x 128h, 256 threads, per-thread 2i x 8h.
// tx = tid&15 owns h = [tx*4, tx*4+4) and [64+tx*4, 64+tx*4+4)  -> conflict-free
// LDS.128 (each 8-lane phase covers 128 contiguous bytes of sH).
// ty = tid>>4 owns i rows {ty*2, ty*2+1}.
// Grid 16 x 64 -> ~512 working blocks (cnt~256): fills 148 SMs.
// ---------------------------------------------------------------------------
__global__ void __launch_bounds__(256, 4) k_gemm(
    const float* __restrict__ h_t,
    float*       __restrict__ out)
{
    int b   = blockIdx.y;
    int cnt = g_jcnt[b];
    int ip0 = blockIdx.x * 32;
    if (ip0 >= cnt) return;
    int cnt32 = (cnt + 31) & ~31;

    int tid = threadIdx.x;
    int tx  = tid & 15;
    int ty  = tid >> 4;

    __shared__ __align__(16) float sW[32][36];   // 144B rows: aligned, bank-delta 4/row
    __shared__ __align__(16) float sH[32][128];
    __shared__ int s_jl[NN];
    __shared__ int s_il[32];

    #pragma unroll
    for (int q = 0; q < 2; q++) {
        int jc = tid + q * 256;
        s_jl[jc] = (jc < cnt) ? g_jlist[b][jc] : 0;
    }
    if (tid < 32) {
        int ip = ip0 + tid;
        s_il[tid] = (ip < cnt) ? g_jlist[b][ip] : 0;
    }

    float acc[2][8];
    #pragma unroll
    for (int a = 0; a < 2; a++)
        #pragma unroll
        for (int c = 0; c < 8; c++) acc[a][c] = 0.f;

    const float* hb = h_t + (size_t)b * HH;
    const float* wb = g_wc + ((size_t)b * NN + ip0) * NN;

    for (int kc0 = 0; kc0 < cnt32; kc0 += 32) {
        __syncthreads();

        // W tile 32x32: 256 float4, 1 per thread.
        {
            int ii = tid >> 3;
            int kq = tid & 7;
            float4 v = make_float4(0.f, 0.f, 0.f, 0.f);
            if (ip0 + ii < cnt)
                v = *(const float4*)(wb + (size_t)ii * NN + kc0 + kq * 4);
            *(float4*)(&sW[ii][kq * 4]) = v;
        }
        // H tile 32x128 gathered rows: 1024 float4, 4 per thread.
        #pragma unroll
        for (int rep = 0; rep < 4; rep++) {
            int e  = rep * 256 + tid;
            int kk = e >> 5;
            int h4 = e & 31;
            int j  = s_jl[kc0 + kk];
            float4 hv = *(const float4*)(hb + (size_t)j * (BB * HH) + h4 * 4);
            *(float4*)(&sH[kk][h4 * 4]) = hv;
        }
        __syncthreads();

        #pragma unroll
        for (int kk = 0; kk < 32; kk++) {
            float4 h0 = *(const float4*)(&sH[kk][tx * 4]);
            float4 h1 = *(const float4*)(&sH[kk][64 + tx * 4]);
            #pragma unroll
            for (int a = 0; a < 2; a++) {
                float wv = sW[ty * 2 + a][kk];
                acc[a][0] = fmaf(wv, h0.x, acc[a][0]);
                acc[a][1] = fmaf(wv, h0.y, acc[a][1]);
                acc[a][2] = fmaf(wv, h0.z, acc[a][2]);
                acc[a][3] = fmaf(wv, h0.w, acc[a][3]);
                acc[a][4] = fmaf(wv, h1.x, acc[a][4]);
                acc[a][5] = fmaf(wv, h1.y, acc[a][5]);
                acc[a][6] = fmaf(wv, h1.z, acc[a][6]);
                acc[a][7] = fmaf(wv, h1.w, acc[a][7]);
            }
        }
    }

    float inv = 1.0f / __uint_as_float(g_maxbits);
    #pragma unroll
    for (int a = 0; a < 2; a++) {
        int ipl = ty * 2 + a;
        if (ip0 + ipl < cnt) {
            int i = s_il[ipl];
            float* op = out + ((size_t)(b * NN + i)) * HH;
            float4 o0 = make_float4(acc[a][0] * inv, acc[a][1] * inv,
                                    acc[a][2] * inv, acc[a][3] * inv);
            float4 o1 = make_float4(acc[a][4] * inv, acc[a][5] * inv,
                                    acc[a][6] * inv, acc[a][7] * inv);
            *(float4*)(op + tx * 4)      = o0;
            *(float4*)(op + 64 + tx * 4) = o1;
        }
    }
}

// ---------------------------------------------------------------------------
extern "C" void kernel_launch(void* const* d_in, const int* in_sizes, int n_in,
                              void* d_out, int out_size)
{
    const float* h_t    = (const float*)d_in[0];
    const int*   r_mat  = (const int*)  d_in[1];
    const float* d_mat  = (const float*)d_in[2];
    const float* mask   = (const float*)d_in[3];
    const int*   cog    = (const int*)  d_in[4];
    const float* domain = (const float*)d_in[5];
    float* out = (float*)d_out;

    k_zero_out<<<1024, 256>>>((float4*)out, out_size / 4);
    k_compact<<<BB, NN>>>(mask);
    dim3 g1(NN, BB);
    k_build_w<<<g1, 128>>>(r_mat, d_mat, cog, domain);
    dim3 g2(NN / 32, BB);
    k_gemm<<<g2, 256>>>(h_t, out);
}